// round 2
// baseline (speedup 1.0000x reference)
#include <cuda_runtime.h>
#include <math.h>

#define N_ROWS 8192
#define DIM    512
#define NCLS   10
#define NMAT   32

// ---------------- scratch (static device globals; no allocation) ----------------
__device__ int   g_counts[NCLS];
__device__ int   g_cursor[NCLS];
__device__ int   g_offsets[NCLS];
__device__ int   g_sorted[N_ROWS];
__device__ float g_gram[2 * NCLS][DIM * DIM];   // 0..9: Z class grams, 10..19: Zbar
__device__ float g_M[NMAT][DIM * DIM];          // 32 matrices I + s*G
__device__ double g_logdet[NMAT];

// ---------------- tiny setup kernels ----------------
__global__ void k_zero() {
    int t = threadIdx.x;
    if (t < NCLS) { g_counts[t] = 0; g_cursor[t] = 0; }
}

__global__ void k_hist(const int* __restrict__ lbl) {
    int i = blockIdx.x * blockDim.x + threadIdx.x;
    if (i < N_ROWS) atomicAdd(&g_counts[lbl[i]], 1);
}

__global__ void k_scan() {
    if (threadIdx.x == 0) {
        int acc = 0;
        for (int c = 0; c < NCLS; c++) {
            g_offsets[c] = acc;
            g_cursor[c]  = acc;
            acc += g_counts[c];
        }
    }
}

__global__ void k_scatter(const int* __restrict__ lbl) {
    int i = blockIdx.x * blockDim.x + threadIdx.x;
    if (i < N_ROWS) {
        int p = atomicAdd(&g_cursor[lbl[i]], 1);
        g_sorted[p] = i;
    }
}

// ---------------- per-class Gram GEMM ----------------
// grid.y = m in 0..19 (class c = m%10, source Z or Zbar)
// grid.x = 36 lower-triangular 64x64 tile pairs of the 512x512 output
// block = 256 threads, 4x4 micro-tile per thread, K-chunks of 16 gathered rows
__global__ void __launch_bounds__(256) k_gram(const float* __restrict__ Z,
                                              const float* __restrict__ Zb) {
    int m = blockIdx.y;
    int c = m % NCLS;
    const float* src = (m < NCLS) ? Z : Zb;

    // decode lower-tri tile pair
    int bi = 0, r = blockIdx.x;
    while (r >= bi + 1) { r -= bi + 1; bi++; }
    int bj = r;

    int off = g_offsets[c];
    int cnt = g_counts[c];

    __shared__ __align__(16) float As[16][64];
    __shared__ __align__(16) float Bs[16][64];

    int tid = threadIdx.x;
    int tx = tid & 15, ty = tid >> 4;

    // loader mapping: one float4 per thread per tile-slice
    int kk_l  = tid >> 4;        // chunk row 0..15
    int col_l = (tid & 15) * 4;  // col 0..60

    float acc[4][4];
#pragma unroll
    for (int i = 0; i < 4; i++)
#pragma unroll
        for (int j = 0; j < 4; j++) acc[i][j] = 0.f;

    for (int k0 = 0; k0 < cnt; k0 += 16) {
        float4 av = make_float4(0.f, 0.f, 0.f, 0.f);
        float4 bv = make_float4(0.f, 0.f, 0.f, 0.f);
        int kr = k0 + kk_l;
        if (kr < cnt) {
            int row = g_sorted[off + kr];
            const float* rp = src + (size_t)row * DIM;
            av = *(const float4*)(rp + bi * 64 + col_l);
            bv = *(const float4*)(rp + bj * 64 + col_l);
        }
        __syncthreads();                // previous chunk's compute done
        *(float4*)&As[kk_l][col_l] = av;
        *(float4*)&Bs[kk_l][col_l] = bv;
        __syncthreads();

#pragma unroll
        for (int kk = 0; kk < 16; kk++) {
            float4 a = *(const float4*)&As[kk][ty * 4];
            float4 b = *(const float4*)&Bs[kk][tx * 4];
            float aa[4] = {a.x, a.y, a.z, a.w};
            float bb[4] = {b.x, b.y, b.z, b.w};
#pragma unroll
            for (int i = 0; i < 4; i++)
#pragma unroll
                for (int j = 0; j < 4; j++) acc[i][j] += aa[i] * bb[j];
        }
    }

    float* G = g_gram[m];
#pragma unroll
    for (int i = 0; i < 4; i++) {
        int gi = bi * 64 + ty * 4 + i;
#pragma unroll
        for (int j = 0; j < 4; j++) {
            int gj = bj * 64 + tx * 4 + j;
            G[gi * DIM + gj] = acc[i][j];
            if (bi != bj) G[gj * DIM + gi] = acc[i][j];
        }
    }
}

// ---------------- build the 32 matrices M = I + s*G ----------------
// grid = (512 rows, 32 matrices), block = 128 threads (4 cols / thread)
__global__ void __launch_bounds__(128) k_buildM() {
    int m   = blockIdx.y;
    int row = blockIdx.x;
    int col = threadIdx.x * 4;

    float4 v;
    if (m < 10) {
        float cnt = (float)g_counts[m];
        float s = 512.f / ((cnt + 1e-8f) * 0.5f);
        float4 g = *(const float4*)&g_gram[m][row * DIM + col];
        v = make_float4(s * g.x, s * g.y, s * g.z, s * g.w);
    } else if (m < 20) {
        float cnt = (float)g_counts[m - 10];
        float s = 512.f / ((cnt + 1e-8f) * 0.5f);
        float4 g = *(const float4*)&g_gram[m][row * DIM + col];
        v = make_float4(s * g.x, s * g.y, s * g.z, s * g.w);
    } else if (m < 30) {
        int c = m - 20;
        float cnt = (float)g_counts[c];
        float s = 512.f / (2.f * cnt * 0.5f);   // d/(2*count*eps)
        float4 g1 = *(const float4*)&g_gram[c][row * DIM + col];
        float4 g2 = *(const float4*)&g_gram[10 + c][row * DIM + col];
        v = make_float4(s * (g1.x + g2.x), s * (g1.y + g2.y),
                        s * (g1.z + g2.z), s * (g1.w + g2.w));
    } else {
        int base = (m == 30) ? 0 : 10;
        float4 s4 = make_float4(0.f, 0.f, 0.f, 0.f);
        for (int c = 0; c < NCLS; c++) {
            float4 g = *(const float4*)&g_gram[base + c][row * DIM + col];
            s4.x += g.x; s4.y += g.y; s4.z += g.z; s4.w += g.w;
        }
        const float s = 0.125f;  // d/(n*eps) = 512/(8192*0.5)
        v = make_float4(s * s4.x, s * s4.y, s * s4.z, s * s4.w);
    }
    // add identity
    if (row >= col && row < col + 4) {
        if (row == col)     v.x += 1.f;
        else if (row == col + 1) v.y += 1.f;
        else if (row == col + 2) v.z += 1.f;
        else                v.w += 1.f;
    }
    *(float4*)&g_M[m][row * DIM + col] = v;
}

// ---------------- blocked Cholesky + logdet, one block per matrix ----------------
#define CNB 16
__global__ void __launch_bounds__(256) k_chol() {
    int m = blockIdx.x;
    float* M = g_M[m];

    __shared__ float sD[CNB][CNB + 1];
    __shared__ float sInv[CNB];
    __shared__ __align__(16) float sPT[CNB][DIM];  // panel transposed: sPT[t][row]
    __shared__ double sLog;

    int tid = threadIdx.x;
    int tx = tid & 15, ty = tid >> 4;
    if (tid == 0) sLog = 0.0;

    for (int p = 0; p < DIM / CNB; p++) {
        int kb = p * CNB;

        // load diagonal block
        if (tid < CNB * CNB) {
            int i = tid / CNB, j = tid % CNB;
            sD[i][j] = M[(size_t)(kb + i) * DIM + kb + j];
        }
        __syncthreads();

        // factor diagonal block (unblocked)
        for (int j = 0; j < CNB; j++) {
            if (tid == 0) {
                float d = sD[j][j];
                sLog += (double)logf(d);       // logdet accumulates log(L_kk^2)
                float inv = rsqrtf(d);
                sInv[j] = inv;
                sD[j][j] = d * inv;            // sqrt(d)
            }
            __syncthreads();
            if (tid >= j + 1 && tid < CNB) sD[tid][j] *= sInv[j];
            __syncthreads();
            if (tid < CNB * CNB) {
                int i = tid / CNB, j2 = tid % CNB;
                if (i >= j2 && j2 > j) sD[i][j2] -= sD[i][j] * sD[j2][j];  // FIX: include diagonal (i==j2)
            }
            __syncthreads();
        }

        int nr = DIM - kb - CNB;   // trailing size
        if (nr == 0) break;

        // panel solve: rows kb+16..511, forward substitution against L11
        for (int rr = tid; rr < nr; rr += 256) {
            const float* mr = M + (size_t)(kb + CNB + rr) * DIM + kb;
            float x[CNB];
            float4 x0 = *(const float4*)(mr + 0);
            float4 x1 = *(const float4*)(mr + 4);
            float4 x2 = *(const float4*)(mr + 8);
            float4 x3 = *(const float4*)(mr + 12);
            x[0]=x0.x; x[1]=x0.y; x[2]=x0.z; x[3]=x0.w;
            x[4]=x1.x; x[5]=x1.y; x[6]=x1.z; x[7]=x1.w;
            x[8]=x2.x; x[9]=x2.y; x[10]=x2.z; x[11]=x2.w;
            x[12]=x3.x; x[13]=x3.y; x[14]=x3.z; x[15]=x3.w;
#pragma unroll
            for (int j = 0; j < CNB; j++) {
                float s = x[j];
#pragma unroll
                for (int t = 0; t < CNB; t++)
                    if (t < j) s -= x[t] * sD[j][t];
                x[j] = s * sInv[j];
            }
#pragma unroll
            for (int j = 0; j < CNB; j++) sPT[j][rr] = x[j];
        }
        __syncthreads();

        // trailing SYRK: M22 -= P P^T (lower triangle, 64x64 tiles, 4x4 micro)
        int base = kb + CNB;
        int nT = (nr + 63) / 64;
        for (int ti = 0; ti < nT; ti++) {
            for (int tj = 0; tj <= ti; tj++) {
                int r0 = ti * 64, c0 = tj * 64;
                int riB = r0 + ty * 4;     // local row base
                int cjB = c0 + tx * 4;     // local col base
                bool cok = (cjB < nr);
                float acc[4][4];
#pragma unroll
                for (int i = 0; i < 4; i++) {
                    int ri = riB + i;
                    if (ri < nr && cok) {
                        float4 mv = *(const float4*)&M[(size_t)(base + ri) * DIM + base + cjB];
                        acc[i][0] = mv.x; acc[i][1] = mv.y; acc[i][2] = mv.z; acc[i][3] = mv.w;
                    } else {
                        acc[i][0] = acc[i][1] = acc[i][2] = acc[i][3] = 0.f;
                    }
                }
#pragma unroll
                for (int t = 0; t < CNB; t++) {
                    float4 a = *(const float4*)&sPT[t][riB];
                    float4 b = *(const float4*)&sPT[t][cjB];
                    float aa[4] = {a.x, a.y, a.z, a.w};
                    float bb[4] = {b.x, b.y, b.z, b.w};
#pragma unroll
                    for (int i = 0; i < 4; i++)
#pragma unroll
                        for (int j = 0; j < 4; j++) acc[i][j] -= aa[i] * bb[j];
                }
#pragma unroll
                for (int i = 0; i < 4; i++) {
                    int ri = riB + i;
                    if (ri < nr && cok) {
                        float4 mv = make_float4(acc[i][0], acc[i][1], acc[i][2], acc[i][3]);
                        *(float4*)&M[(size_t)(base + ri) * DIM + base + cjB] = mv;
                    }
                }
            }
        }
        __syncthreads();   // M + sPT consistent before next panel
    }
    if (tid == 0) g_logdet[m] = sLog;
}

// ---------------- combine into the 4 outputs ----------------
__global__ void k_combine(float* __restrict__ out) {
    if (threadIdx.x == 0) {
        double sum_ldz = 0.0, sum_ldzb = 0.0, comp_z = 0.0, comp_zb = 0.0, item = 0.0;
        for (int c = 0; c < NCLS; c++) {
            double cnt = (double)g_counts[c];
            double w = (cnt + 1e-8) / (2.0 * (double)N_ROWS);
            double ldz  = g_logdet[c];
            double ldzb = g_logdet[10 + c];
            sum_ldz  += ldz;
            sum_ldzb += ldzb;
            comp_z   += w * ldz;
            comp_zb  += w * ldzb;
            item     += 0.5 * g_logdet[20 + c];
        }
        double disc_z  = 0.5 * g_logdet[30];
        double disc_zb = 0.5 * g_logdet[31];
        double t1 = disc_z - comp_z;
        double t2 = disc_zb - comp_zb;
        double term3 = item - 0.25 * sum_ldz - 0.25 * sum_ldzb;
        out[0] = (float)(-(t1 + t2 + term3));
        out[1] = (float)(-t1);
        out[2] = (float)(-t2);
        out[3] = (float)term3;
    }
}

// ---------------- launch ----------------
extern "C" void kernel_launch(void* const* d_in, const int* in_sizes, int n_in,
                              void* d_out, int out_size) {
    const float* Z   = (const float*)d_in[0];
    const float* Zb  = (const float*)d_in[1];
    const int*   lbl = (const int*)d_in[2];
    float* out = (float*)d_out;

    k_zero<<<1, 32>>>();
    k_hist<<<N_ROWS / 256, 256>>>(lbl);
    k_scan<<<1, 32>>>();
    k_scatter<<<N_ROWS / 256, 256>>>(lbl);
    k_gram<<<dim3(36, 20), 256>>>(Z, Zb);
    k_buildM<<<dim3(DIM, NMAT), 128>>>();
    k_chol<<<NMAT, 256>>>();
    k_combine<<<1, 32>>>(out);
}

// round 3
// speedup vs baseline: 1.1989x; 1.1989x over previous
#include <cuda_runtime.h>
#include <math.h>

#define N_ROWS 8192
#define DIM    512
#define NCLS   10
#define NMAT   32
#define PNB    32      // panel width for multi-launch cholesky
#define NPANEL 12      // panels cover cols 0..384; final kernel does last 128
#define FINRES 128     // residual block finished in one kernel

// ---------------- scratch (static device globals; no allocation) ----------------
__device__ int    g_counts[NCLS];
__device__ int    g_cursor[NCLS];
__device__ int    g_offsets[NCLS];
__device__ int    g_sorted[N_ROWS];
__device__ float  g_gram[2 * NCLS][DIM * DIM];
__device__ float  g_M[NMAT][DIM * DIM];
__device__ float  g_P[NMAT][(DIM - PNB) * PNB];   // solved panel, trailing-relative rows
__device__ double g_logdet[NMAT];

// ---------------- tiny setup kernels ----------------
__global__ void k_zero() {
    int t = threadIdx.x;
    if (t < NCLS) { g_counts[t] = 0; g_cursor[t] = 0; }
    if (t < NMAT) g_logdet[t] = 0.0;
}

__global__ void k_hist(const int* __restrict__ lbl) {
    int i = blockIdx.x * blockDim.x + threadIdx.x;
    if (i < N_ROWS) atomicAdd(&g_counts[lbl[i]], 1);
}

__global__ void k_scan() {
    if (threadIdx.x == 0) {
        int acc = 0;
        for (int c = 0; c < NCLS; c++) {
            g_offsets[c] = acc;
            g_cursor[c]  = acc;
            acc += g_counts[c];
        }
    }
}

__global__ void k_scatter(const int* __restrict__ lbl) {
    int i = blockIdx.x * blockDim.x + threadIdx.x;
    if (i < N_ROWS) {
        int p = atomicAdd(&g_cursor[lbl[i]], 1);
        g_sorted[p] = i;
    }
}

// ---------------- per-class Gram GEMM (8x8 micro, 64 threads, 64x64 tiles) ----------------
// grid.y = m in 0..19 (class c = m%10, src Z or Zbar); grid.x = 36 lower-tri 64-tile pairs
__global__ void __launch_bounds__(64) k_gram(const float* __restrict__ Z,
                                             const float* __restrict__ Zb) {
    int m = blockIdx.y;
    int c = m % NCLS;
    const float* src = (m < NCLS) ? Z : Zb;

    int bi = 0, r = blockIdx.x;
    while (r >= bi + 1) { r -= bi + 1; bi++; }
    int bj = r;

    int off = g_offsets[c];
    int cnt = g_counts[c];

    __shared__ __align__(16) float sA[32][64];
    __shared__ __align__(16) float sB[32][64];

    int tid = threadIdx.x;
    int tx = tid & 7, ty = tid >> 3;

    float acc[8][8];
#pragma unroll
    for (int i = 0; i < 8; i++)
#pragma unroll
        for (int j = 0; j < 8; j++) acc[i][j] = 0.f;

    for (int k0 = 0; k0 < cnt; k0 += 32) {
        __syncthreads();   // previous chunk's compute done
        // load: per side 32 k-rows x 16 float4 = 512 float4; this thread does 8 per side
#pragma unroll
        for (int it = 0; it < 8; it++) {
            int t = tid + it * 64;
            int k = t >> 4, q = t & 15;
            int kr = k0 + k;
            float4 va = make_float4(0.f, 0.f, 0.f, 0.f);
            float4 vb = va;
            if (kr < cnt) {
                int row = g_sorted[off + kr];
                const float* rp = src + (size_t)row * DIM;
                va = *(const float4*)(rp + bi * 64 + q * 4);
                vb = *(const float4*)(rp + bj * 64 + q * 4);
            }
            *(float4*)&sA[k][q * 4] = va;
            *(float4*)&sB[k][q * 4] = vb;
        }
        __syncthreads();

#pragma unroll 8
        for (int k = 0; k < 32; k++) {
            float4 a0 = *(const float4*)&sA[k][ty * 8];
            float4 a1 = *(const float4*)&sA[k][ty * 8 + 4];
            float4 b0 = *(const float4*)&sB[k][tx * 8];
            float4 b1 = *(const float4*)&sB[k][tx * 8 + 4];
            float aa[8] = {a0.x, a0.y, a0.z, a0.w, a1.x, a1.y, a1.z, a1.w};
            float bb[8] = {b0.x, b0.y, b0.z, b0.w, b1.x, b1.y, b1.z, b1.w};
#pragma unroll
            for (int i = 0; i < 8; i++)
#pragma unroll
                for (int j = 0; j < 8; j++) acc[i][j] += aa[i] * bb[j];
        }
    }

    float* G = g_gram[m];
#pragma unroll
    for (int i = 0; i < 8; i++) {
        int gi = bi * 64 + ty * 8 + i;
        float4 v0 = make_float4(acc[i][0], acc[i][1], acc[i][2], acc[i][3]);
        float4 v1 = make_float4(acc[i][4], acc[i][5], acc[i][6], acc[i][7]);
        int gj = bj * 64 + tx * 8;
        *(float4*)&G[(size_t)gi * DIM + gj]     = v0;
        *(float4*)&G[(size_t)gi * DIM + gj + 4] = v1;
        if (bi != bj) {
#pragma unroll
            for (int j = 0; j < 8; j++)
                G[(size_t)(gj + j) * DIM + gi] = acc[i][j];
        }
    }
}

// ---------------- build the 32 matrices M = I + s*G ----------------
__global__ void __launch_bounds__(128) k_buildM() {
    int m   = blockIdx.y;
    int row = blockIdx.x;
    int col = threadIdx.x * 4;

    float4 v;
    if (m < 20) {
        int c = (m < 10) ? m : (m - 10);
        float cnt = (float)g_counts[c];
        float s = 512.f / ((cnt + 1e-8f) * 0.5f);
        float4 g = *(const float4*)&g_gram[m][row * DIM + col];
        v = make_float4(s * g.x, s * g.y, s * g.z, s * g.w);
    } else if (m < 30) {
        int c = m - 20;
        float cnt = (float)g_counts[c];
        float s = 512.f / (2.f * cnt * 0.5f);
        float4 g1 = *(const float4*)&g_gram[c][row * DIM + col];
        float4 g2 = *(const float4*)&g_gram[10 + c][row * DIM + col];
        v = make_float4(s * (g1.x + g2.x), s * (g1.y + g2.y),
                        s * (g1.z + g2.z), s * (g1.w + g2.w));
    } else {
        int base = (m == 30) ? 0 : 10;
        float4 s4 = make_float4(0.f, 0.f, 0.f, 0.f);
        for (int c = 0; c < NCLS; c++) {
            float4 g = *(const float4*)&g_gram[base + c][row * DIM + col];
            s4.x += g.x; s4.y += g.y; s4.z += g.z; s4.w += g.w;
        }
        const float s = 0.125f;
        v = make_float4(s * s4.x, s * s4.y, s * s4.z, s * s4.w);
    }
    if (row >= col && row < col + 4) {
        if (row == col)          v.x += 1.f;
        else if (row == col + 1) v.y += 1.f;
        else if (row == col + 2) v.z += 1.f;
        else                     v.w += 1.f;
    }
    *(float4*)&g_M[m][row * DIM + col] = v;
}

// ---------------- panel factor: 32x32 diag (warp-register chol) + panel solve ----------------
// grid = NMAT blocks, 256 threads
__global__ void __launch_bounds__(256) k_panelA(int kb) {
    int m = blockIdx.x;
    float* M = g_M[m];
    __shared__ float sD[PNB][PNB + 1];
    __shared__ float sInv[PNB];

    int tid = threadIdx.x;
    int nr = DIM - kb - PNB;

    if (tid < 32) {
        int r = tid;
        float a[32];
        const float* rp = M + (size_t)(kb + r) * DIM + kb;
#pragma unroll
        for (int t4 = 0; t4 < 8; t4++) {
            float4 v = *(const float4*)(rp + t4 * 4);
            a[t4 * 4 + 0] = v.x; a[t4 * 4 + 1] = v.y;
            a[t4 * 4 + 2] = v.z; a[t4 * 4 + 3] = v.w;
        }
        float myinv = 0.f;
        double llog = 0.0;
#pragma unroll
        for (int j = 0; j < 32; j++) {
            float d = __shfl_sync(0xffffffffu, a[j], j);
            float inv = rsqrtf(d);
            if (r == j) { llog = (double)logf(d); myinv = inv; a[j] = d * inv; }
            else if (r > j) a[j] *= inv;
#pragma unroll
            for (int c2 = j + 1; c2 < 32; c2++) {
                float lcj = __shfl_sync(0xffffffffu, a[j], c2);
                if (r >= c2) a[c2] -= a[j] * lcj;
            }
        }
#pragma unroll
        for (int t = 0; t < 32; t++) sD[r][t] = a[t];
        sInv[r] = myinv;
        double tot = llog;
#pragma unroll
        for (int o = 16; o; o >>= 1) tot += __shfl_xor_sync(0xffffffffu, tot, o);
        if (r == 0) g_logdet[m] += tot;
    }
    __syncthreads();

    // panel solve: two rows per thread
    int r0 = tid, r1 = tid + 256;
    bool ok0 = r0 < nr, ok1 = r1 < nr;
    float x0[32], x1[32];
    if (ok0) {
        const float* mr = M + (size_t)(kb + PNB + r0) * DIM + kb;
#pragma unroll
        for (int t4 = 0; t4 < 8; t4++) {
            float4 v = *(const float4*)(mr + t4 * 4);
            x0[t4*4+0]=v.x; x0[t4*4+1]=v.y; x0[t4*4+2]=v.z; x0[t4*4+3]=v.w;
        }
    }
    if (ok1) {
        const float* mr = M + (size_t)(kb + PNB + r1) * DIM + kb;
#pragma unroll
        for (int t4 = 0; t4 < 8; t4++) {
            float4 v = *(const float4*)(mr + t4 * 4);
            x1[t4*4+0]=v.x; x1[t4*4+1]=v.y; x1[t4*4+2]=v.z; x1[t4*4+3]=v.w;
        }
    }
#pragma unroll
    for (int j = 0; j < 32; j++) {
        float s0 = ok0 ? x0[j] : 0.f;
        float s1 = ok1 ? x1[j] : 0.f;
#pragma unroll
        for (int t = 0; t < 32; t++) {
            if (t < j) {
                float l = sD[j][t];
                s0 -= x0[t] * l;
                s1 -= x1[t] * l;
            }
        }
        float iv = sInv[j];
        x0[j] = s0 * iv;
        x1[j] = s1 * iv;
    }
    if (ok0) {
        float* pp = g_P[m] + (size_t)r0 * PNB;
#pragma unroll
        for (int t4 = 0; t4 < 8; t4++)
            *(float4*)(pp + t4 * 4) = make_float4(x0[t4*4], x0[t4*4+1], x0[t4*4+2], x0[t4*4+3]);
    }
    if (ok1) {
        float* pp = g_P[m] + (size_t)r1 * PNB;
#pragma unroll
        for (int t4 = 0; t4 < 8; t4++)
            *(float4*)(pp + t4 * 4) = make_float4(x1[t4*4], x1[t4*4+1], x1[t4*4+2], x1[t4*4+3]);
    }
}

// ---------------- trailing SYRK: M22 -= P P^T (lower only), chip-wide ----------------
// grid = (nt*(nt+1)/2, NMAT), 64 threads, 64x64 tiles, 8x8 micro
__global__ void __launch_bounds__(64) k_syrkB(int kb) {
    int m = blockIdx.y;
    int nr = DIM - kb - PNB;

    int ti = 0, rr = blockIdx.x;
    while (rr >= ti + 1) { rr -= ti + 1; ti++; }
    int tj = rr;

    __shared__ float sA[64][33];
    __shared__ float sB[64][33];

    const float* P = g_P[m];
    float* M = g_M[m];
    int tid = threadIdx.x;
    int tx = tid & 7, ty = tid >> 3;

    // load P tiles (guard row < nr)
#pragma unroll
    for (int it = 0; it < 8; it++) {
        int t = tid + it * 64;
        int row = t >> 3, q = t & 7;
        int ra = ti * 64 + row;
        float4 va = (ra < nr) ? *(const float4*)(P + (size_t)ra * PNB + q * 4)
                              : make_float4(0.f, 0.f, 0.f, 0.f);
        sA[row][q*4+0]=va.x; sA[row][q*4+1]=va.y; sA[row][q*4+2]=va.z; sA[row][q*4+3]=va.w;
        int rb = tj * 64 + row;
        float4 vb = (rb < nr) ? *(const float4*)(P + (size_t)rb * PNB + q * 4)
                              : make_float4(0.f, 0.f, 0.f, 0.f);
        sB[row][q*4+0]=vb.x; sB[row][q*4+1]=vb.y; sB[row][q*4+2]=vb.z; sB[row][q*4+3]=vb.w;
    }
    __syncthreads();

    float acc[8][8];
#pragma unroll
    for (int i = 0; i < 8; i++)
#pragma unroll
        for (int j = 0; j < 8; j++) acc[i][j] = 0.f;

#pragma unroll 4
    for (int k = 0; k < PNB; k++) {
        float aa[8], bb[8];
#pragma unroll
        for (int i = 0; i < 8; i++) aa[i] = sA[ty * 8 + i][k];
#pragma unroll
        for (int j = 0; j < 8; j++) bb[j] = sB[tx * 8 + j][k];
#pragma unroll
        for (int i = 0; i < 8; i++)
#pragma unroll
            for (int j = 0; j < 8; j++) acc[i][j] += aa[i] * bb[j];
    }

    int base = kb + PNB;
    if (ti != tj) {
#pragma unroll
        for (int i = 0; i < 8; i++) {
            int rl = ti * 64 + ty * 8 + i;
            if (rl < nr) {
                float* mp = M + (size_t)(base + rl) * DIM + base + tj * 64 + tx * 8;
                float4 v0 = *(float4*)mp;
                float4 v1 = *(float4*)(mp + 4);
                v0.x -= acc[i][0]; v0.y -= acc[i][1]; v0.z -= acc[i][2]; v0.w -= acc[i][3];
                v1.x -= acc[i][4]; v1.y -= acc[i][5]; v1.z -= acc[i][6]; v1.w -= acc[i][7];
                *(float4*)mp = v0;
                *(float4*)(mp + 4) = v1;
            }
        }
    } else {
#pragma unroll
        for (int i = 0; i < 8; i++) {
            int rl = ti * 64 + ty * 8 + i;
            if (rl < nr) {
                float* mp = M + (size_t)(base + rl) * DIM + base;
#pragma unroll
                for (int j = 0; j < 8; j++) {
                    int cl = tj * 64 + tx * 8 + j;
                    if (cl <= rl && cl < nr) mp[cl] -= acc[i][j];
                }
            }
        }
    }
}

// ---------------- finish last 128x128 block per matrix (R2-style blocked chol) ----------------
#define CNB 16
__global__ void __launch_bounds__(256) k_cholfin() {
    int m = blockIdx.x;
    float* M = g_M[m];

    __shared__ float sD[CNB][CNB + 1];
    __shared__ float sInv[CNB];
    __shared__ __align__(16) float sPT[CNB][FINRES];
    __shared__ double sLog;

    int tid = threadIdx.x;
    int tx = tid & 15, ty = tid >> 4;
    if (tid == 0) sLog = 0.0;

    for (int kb = DIM - FINRES; kb < DIM; kb += CNB) {
        if (tid < CNB * CNB) {
            int i = tid / CNB, j = tid % CNB;
            sD[i][j] = M[(size_t)(kb + i) * DIM + kb + j];
        }
        __syncthreads();

        for (int j = 0; j < CNB; j++) {
            if (tid == 0) {
                float d = sD[j][j];
                sLog += (double)logf(d);
                float inv = rsqrtf(d);
                sInv[j] = inv;
                sD[j][j] = d * inv;
            }
            __syncthreads();
            if (tid >= j + 1 && tid < CNB) sD[tid][j] *= sInv[j];
            __syncthreads();
            if (tid < CNB * CNB) {
                int i = tid / CNB, j2 = tid % CNB;
                if (i >= j2 && j2 > j) sD[i][j2] -= sD[i][j] * sD[j2][j];
            }
            __syncthreads();
        }

        int nr = DIM - kb - CNB;
        if (nr == 0) break;

        for (int rr2 = tid; rr2 < nr; rr2 += 256) {
            const float* mr = M + (size_t)(kb + CNB + rr2) * DIM + kb;
            float x[CNB];
            float4 x0 = *(const float4*)(mr + 0);
            float4 x1 = *(const float4*)(mr + 4);
            float4 x2 = *(const float4*)(mr + 8);
            float4 x3 = *(const float4*)(mr + 12);
            x[0]=x0.x; x[1]=x0.y; x[2]=x0.z; x[3]=x0.w;
            x[4]=x1.x; x[5]=x1.y; x[6]=x1.z; x[7]=x1.w;
            x[8]=x2.x; x[9]=x2.y; x[10]=x2.z; x[11]=x2.w;
            x[12]=x3.x; x[13]=x3.y; x[14]=x3.z; x[15]=x3.w;
#pragma unroll
            for (int j = 0; j < CNB; j++) {
                float s = x[j];
#pragma unroll
                for (int t = 0; t < CNB; t++)
                    if (t < j) s -= x[t] * sD[j][t];
                x[j] = s * sInv[j];
            }
#pragma unroll
            for (int j = 0; j < CNB; j++) sPT[j][rr2] = x[j];
        }
        __syncthreads();

        int base = kb + CNB;
        int nT = (nr + 63) / 64;
        for (int ti = 0; ti < nT; ti++) {
            for (int tj = 0; tj <= ti; tj++) {
                int riB = ti * 64 + ty * 4;
                int cjB = tj * 64 + tx * 4;
                bool cok = (cjB < nr);
                float acc[4][4];
#pragma unroll
                for (int i = 0; i < 4; i++) {
                    int ri = riB + i;
                    if (ri < nr && cok) {
                        float4 mv = *(const float4*)&M[(size_t)(base + ri) * DIM + base + cjB];
                        acc[i][0] = mv.x; acc[i][1] = mv.y; acc[i][2] = mv.z; acc[i][3] = mv.w;
                    } else {
                        acc[i][0] = acc[i][1] = acc[i][2] = acc[i][3] = 0.f;
                    }
                }
#pragma unroll
                for (int t = 0; t < CNB; t++) {
                    float4 a = *(const float4*)&sPT[t][riB];
                    float4 b = *(const float4*)&sPT[t][cjB];
                    float aa[4] = {a.x, a.y, a.z, a.w};
                    float bb[4] = {b.x, b.y, b.z, b.w};
#pragma unroll
                    for (int i = 0; i < 4; i++)
#pragma unroll
                        for (int j = 0; j < 4; j++) acc[i][j] -= aa[i] * bb[j];
                }
#pragma unroll
                for (int i = 0; i < 4; i++) {
                    int ri = riB + i;
                    if (ri < nr && cok) {
                        float4 mv = make_float4(acc[i][0], acc[i][1], acc[i][2], acc[i][3]);
                        *(float4*)&M[(size_t)(base + ri) * DIM + base + cjB] = mv;
                    }
                }
            }
        }
        __syncthreads();
    }
    if (tid == 0) g_logdet[m] += sLog;
}

// ---------------- combine into the 4 outputs ----------------
__global__ void k_combine(float* __restrict__ out) {
    if (threadIdx.x == 0) {
        double sum_ldz = 0.0, sum_ldzb = 0.0, comp_z = 0.0, comp_zb = 0.0, item = 0.0;
        for (int c = 0; c < NCLS; c++) {
            double cnt = (double)g_counts[c];
            double w = (cnt + 1e-8) / (2.0 * (double)N_ROWS);
            double ldz  = g_logdet[c];
            double ldzb = g_logdet[10 + c];
            sum_ldz  += ldz;
            sum_ldzb += ldzb;
            comp_z   += w * ldz;
            comp_zb  += w * ldzb;
            item     += 0.5 * g_logdet[20 + c];
        }
        double disc_z  = 0.5 * g_logdet[30];
        double disc_zb = 0.5 * g_logdet[31];
        double t1 = disc_z - comp_z;
        double t2 = disc_zb - comp_zb;
        double term3 = item - 0.25 * sum_ldz - 0.25 * sum_ldzb;
        out[0] = (float)(-(t1 + t2 + term3));
        out[1] = (float)(-t1);
        out[2] = (float)(-t2);
        out[3] = (float)term3;
    }
}

// ---------------- launch ----------------
extern "C" void kernel_launch(void* const* d_in, const int* in_sizes, int n_in,
                              void* d_out, int out_size) {
    const float* Z   = (const float*)d_in[0];
    const float* Zb  = (const float*)d_in[1];
    const int*   lbl = (const int*)d_in[2];
    float* out = (float*)d_out;

    k_zero<<<1, 64>>>();
    k_hist<<<N_ROWS / 256, 256>>>(lbl);
    k_scan<<<1, 32>>>();
    k_scatter<<<N_ROWS / 256, 256>>>(lbl);
    k_gram<<<dim3(36, 20), 64>>>(Z, Zb);
    k_buildM<<<dim3(DIM, NMAT), 128>>>();

    for (int p = 0; p < NPANEL; p++) {
        int kb = p * PNB;
        k_panelA<<<NMAT, 256>>>(kb);
        int nr = DIM - kb - PNB;
        int nt = (nr + 63) / 64;
        k_syrkB<<<dim3(nt * (nt + 1) / 2, NMAT), 64>>>(kb);
    }
    k_cholfin<<<NMAT, 256>>>();
    k_combine<<<1, 32>>>(out);
}